// round 1
// baseline (speedup 1.0000x reference)
#include <cuda_runtime.h>
#include <cuda_bf16.h>
#include <cstdint>

// Unfold3d: x (B=4, C=32, D=16, H=48, W=48) fp32, K=3, PAD=1, STR=1, DIL=1.
// Output: (B, C*27, Do*Ho*Wo) with Do=16, Ho=48, Wo=48.
// out[b][c*27 + kidx][d*Ho*Wo + h*Wo + w] = xpad[b][c][d+kd][h+kh][w+kw]
//   where kidx = (kd*3 + kh)*3 + kw, and xpad has 1-padding (zeros).
// i.e. reads x[b][c][d+kd-1][h+kh-1][w+kw-1] with zero for OOB.

#define B_  4
#define C_  32
#define D_  16
#define H_  48
#define W_  48
#define KK  27
#define W4  (W_ / 4)          // 12 float4 per output row
#define TOTAL4 (B_ * C_ * KK * D_ * H_ * W4)   // 31,850,496

__global__ __launch_bounds__(256) void unfold3d_kernel(
    const float* __restrict__ x, float* __restrict__ out)
{
    int idx = blockIdx.x * blockDim.x + threadIdx.x;
    if (idx >= TOTAL4) return;

    // Decompose idx -> (b, c, kidx, d, h, w4). All divisors are compile-time
    // constants; ptxas turns these into mulhi sequences.
    int w4   = idx % W4;   int t = idx / W4;
    int h    = t % H_;     t /= H_;
    int d    = t % D_;     t /= D_;
    int kidx = t % KK;     t /= KK;
    int c    = t % C_;
    int b    = t / C_;

    int kw = kidx % 3;
    int km = kidx / 3;
    int kh = km % 3;
    int kd = km / 3;

    int dd = d + kd - 1;   // input depth, valid [0, D_)
    int hh = h + kh - 1;   // input height, valid [0, H_)

    float4 v = make_float4(0.f, 0.f, 0.f, 0.f);

    if ((unsigned)dd < (unsigned)D_ && (unsigned)hh < (unsigned)H_) {
        const float* __restrict__ row =
            x + (((size_t)(b * C_ + c) * D_ + dd) * H_ + hh) * W_;
        int w0 = w4 * 4 + kw - 1;   // input w for first lane, range [-1, 48]
        // Four predicated scalar loads (address may be unaligned to 16B and
        // may straddle the W boundary by one element). Reads are L2-hits;
        // the kernel is store-bound so LDG issue cost is hidden.
        if ((unsigned)(w0 + 0) < (unsigned)W_) v.x = __ldg(row + w0 + 0);
        if ((unsigned)(w0 + 1) < (unsigned)W_) v.y = __ldg(row + w0 + 1);
        if ((unsigned)(w0 + 2) < (unsigned)W_) v.z = __ldg(row + w0 + 2);
        if ((unsigned)(w0 + 3) < (unsigned)W_) v.w = __ldg(row + w0 + 3);
    }

    reinterpret_cast<float4*>(out)[idx] = v;
}

extern "C" void kernel_launch(void* const* d_in, const int* in_sizes, int n_in,
                              void* d_out, int out_size)
{
    const float* x = (const float*)d_in[0];
    float* out = (float*)d_out;

    constexpr int threads = 256;
    constexpr int blocks  = (TOTAL4 + threads - 1) / threads;  // 124,416
    unfold3d_kernel<<<blocks, threads>>>(x, out);
}

// round 2
// speedup vs baseline: 1.4235x; 1.4235x over previous
#include <cuda_runtime.h>
#include <cuda_bf16.h>
#include <cstdint>

// Unfold3d: x (B=4, C=32, D=16, H=48, W=48) fp32, K=3, PAD=1, STR=1, DIL=1.
// out[b][c*27 + kidx][d*H*W + h*W + w] = x[b][c][d+kd-1][h+kh-1][w+kw-1] (0 if OOB)
//
// R2: ALU-bound fix. 3D grid carries (d, kidx, b*c); 2D block carries (w4, h).
// Each thread stores 3 float4 (h, h+16, h+32). kw uniform per block ->
// uniform-branch specialized read path: 1 LDG.128 (+1 predicated scalar for
// shifted cases) per float4 instead of 4 scalar loads.

#define B_  4
#define C_  32
#define D_  16
#define H_  48
#define W_  48
#define KK  27
#define W4  (W_ / 4)          // 12
#define HW  (H_ * W_)         // 2304
#define DHW (D_ * HW)

__global__ __launch_bounds__(192) void unfold3d_kernel(
    const float* __restrict__ x, float* __restrict__ out)
{
    const int d    = blockIdx.x;        // 0..15
    const int kidx = blockIdx.y;        // 0..26
    const int bc   = blockIdx.z;        // 0..127  (b*C_ + c)

    const int kw = kidx % 3;
    const int km = kidx / 3;
    const int kh = km % 3;
    const int kd = km / 3;

    const int dd = d + kd - 1;
    const bool dok = (unsigned)dd < (unsigned)D_;

    const int w4 = threadIdx.x;         // 0..11
    const int hb = threadIdx.y;         // 0..15

    const float* __restrict__ plane = x + (size_t)bc * DHW + (size_t)dd * HW;
    // out channel = bc*KK + kidx ; spatial base = d*HW
    float4* __restrict__ ob = reinterpret_cast<float4*>(
        out + ((size_t)(bc * KK + kidx) * D_ + d) * HW);

    #pragma unroll
    for (int i = 0; i < 3; i++) {
        const int h  = hb + i * 16;
        const int hh = h + kh - 1;
        float4 v = make_float4(0.f, 0.f, 0.f, 0.f);

        if (dok && (unsigned)hh < (unsigned)H_) {
            const float* __restrict__ row = plane + hh * W_;
            if (kw == 1) {
                // aligned, always fully in-bounds (w = 4*w4 .. 4*w4+3 <= 47)
                v = *reinterpret_cast<const float4*>(row + w4 * 4);
            } else if (kw == 0) {
                // needs w-1 .. w+2 : rotate aligned vector right by one
                float4 cur = *reinterpret_cast<const float4*>(row + w4 * 4);
                float prevw = 0.f;
                if (w4 > 0) prevw = __ldg(row + w4 * 4 - 1);
                v = make_float4(prevw, cur.x, cur.y, cur.z);
            } else {
                // kw == 2: needs w+1 .. w+4 : rotate left by one
                float4 cur = *reinterpret_cast<const float4*>(row + w4 * 4);
                float nextx = 0.f;
                if (w4 < W4 - 1) nextx = __ldg(row + w4 * 4 + 4);
                v = make_float4(cur.y, cur.z, cur.w, nextx);
            }
        }
        ob[h * W4 + w4] = v;
    }
}

extern "C" void kernel_launch(void* const* d_in, const int* in_sizes, int n_in,
                              void* d_out, int out_size)
{
    const float* x = (const float*)d_in[0];
    float* out = (float*)d_out;

    dim3 grid(D_, KK, B_ * C_);     // 16 x 27 x 128 = 55296 blocks
    dim3 block(W4, 16);             // 12 x 16 = 192 threads
    unfold3d_kernel<<<grid, block>>>(x, out);
}

// round 3
// speedup vs baseline: 1.5828x; 1.1119x over previous
#include <cuda_runtime.h>
#include <cuda_bf16.h>
#include <cstdint>

// Unfold3d: x (B=4, C=32, D=16, H=48, W=48) fp32, K=3, PAD=1, STR=1, DIL=1.
// out[b][c*27 + kidx][d*HW + h*W + w] = x[b][c][d+kd-1][h+kh-1][w+kw-1] (0 OOB)
//
// R3: L2-bandwidth fix. One block per (d, bc). Stage 3 input planes into
// zero-haloed smem [3][50][52]; all output reads come from smem (L2 sees only
// the 510MB write stream + 56MB of reads). Branch-free 3x3x3-unrolled store
// loop; 2 aligned LDS.128 feed all three kw shifts via register selection.

#define B_  4
#define C_  32
#define D_  16
#define H_  48
#define W_  48
#define HW  (H_ * W_)          // 2304
#define DHW (D_ * HW)          // 36864
#define W4  (W_ / 4)           // 12

#define SH  (H_ + 2)           // 50 padded rows
#define SW  52                 // padded row stride (floats); cols 0..49 used
#define SPLANE (SH * SW)       // 2600
#define SMEM_FLOATS (3 * SPLANE)  // 7800 floats = 31200 B

__global__ __launch_bounds__(192) void unfold3d_kernel(
    const float* __restrict__ x, float* __restrict__ out)
{
    __shared__ float s[SMEM_FLOATS];

    const int d  = blockIdx.x;          // 0..15
    const int bc = blockIdx.y;          // 0..127

    const int w4 = threadIdx.x;         // 0..11
    const int hb = threadIdx.y;         // 0..15
    const int tid = hb * 12 + w4;       // 0..191

    // ---- Phase 0: zero-fill smem (vectorized) ----
    {
        float4* s4 = reinterpret_cast<float4*>(s);
        const int n4 = SMEM_FLOATS / 4;             // 1950
        #pragma unroll
        for (int k = 0; k < (n4 + 191) / 192; k++) {
            int i = tid + k * 192;
            if (i < n4) s4[i] = make_float4(0.f, 0.f, 0.f, 0.f);
        }
    }
    __syncthreads();

    // ---- Phase 1: load 3 planes (d-1, d, d+1) into haloed smem ----
    {
        const float* __restrict__ xb = x + (size_t)bc * DHW;
        #pragma unroll
        for (int p = 0; p < 3; p++) {
            const int dd = d + p - 1;
            if ((unsigned)dd < (unsigned)D_) {
                const float* __restrict__ plane = xb + dd * HW;
                float* __restrict__ sp = s + p * SPLANE;
                #pragma unroll
                for (int k = 0; k < 3; k++) {
                    const int row = hb + k * 16;            // 0..47
                    float4 g = *reinterpret_cast<const float4*>(
                        plane + row * W_ + w4 * 4);
                    float* dst = sp + (row + 1) * SW + 1 + w4 * 4;
                    dst[0] = g.x; dst[1] = g.y; dst[2] = g.z; dst[3] = g.w;
                }
            }
        }
    }
    __syncthreads();

    // ---- Phase 2: branch-free store of 27 channel tiles ----
    // out base for this (bc, d): channel bc*27, spatial d*HW
    float* __restrict__ ob = out + (size_t)bc * 27 * DHW + (size_t)d * HW;

    #pragma unroll
    for (int kd = 0; kd < 3; kd++) {
        const float* __restrict__ sp = s + kd * SPLANE;
        #pragma unroll
        for (int kh = 0; kh < 3; kh++) {
            #pragma unroll
            for (int k = 0; k < 3; k++) {
                const int h = hb + k * 16;                  // 0..47
                const float* __restrict__ row = sp + (h + kh) * SW + w4 * 4;
                // q0 = cols [4w4 .. 4w4+3], q1 = cols [4w4+4 .. 4w4+7]
                float4 q0 = *reinterpret_cast<const float4*>(row);
                float4 q1 = *reinterpret_cast<const float4*>(row + 4);

                float* o = ob + (size_t)((kd * 3 + kh) * 3) * DHW
                              + h * W_ + w4 * 4;
                // kw = 0: window cols 4w4..+3
                *reinterpret_cast<float4*>(o) = q0;
                // kw = 1: cols 4w4+1..+4
                *reinterpret_cast<float4*>(o + DHW) =
                    make_float4(q0.y, q0.z, q0.w, q1.x);
                // kw = 2: cols 4w4+2..+5
                *reinterpret_cast<float4*>(o + 2 * DHW) =
                    make_float4(q0.z, q0.w, q1.x, q1.y);
            }
        }
    }
}

extern "C" void kernel_launch(void* const* d_in, const int* in_sizes, int n_in,
                              void* d_out, int out_size)
{
    const float* x = (const float*)d_in[0];
    float* out = (float*)d_out;

    dim3 grid(D_, B_ * C_);        // 16 x 128 = 2048 blocks
    dim3 block(W4, 16);            // 192 threads
    unfold3d_kernel<<<grid, block>>>(x, out);
}

// round 4
// speedup vs baseline: 1.6917x; 1.0687x over previous
#include <cuda_runtime.h>
#include <cuda_bf16.h>
#include <cstdint>

// Unfold3d: x (B=4, C=32, D=16, H=48, W=48) fp32, K=3, PAD=1, STR=1, DIL=1.
// out[b][c*27 + kidx][d*HW + h*W + w] = x[b][c][d+kd-1][h+kh-1][w+kw-1] (0 OOB)
//
// R4: occupancy/MLP fix. Same smem-staged structure as R3, but:
//  - all unrolled store/load offsets are compile-time immediates off one base
//    register per k-iteration (32-bit indexing) -> regs drop ~52 -> <=48
//  - __launch_bounds__(192, 7): 7 CTAs/SM (smem 31.2KB x 7 = 218KB fits)
//  - __stcs streaming stores (write-once output, evict-first in L2)

#define B_  4
#define C_  32
#define D_  16
#define H_  48
#define W_  48
#define HW  (H_ * W_)          // 2304
#define DHW (D_ * HW)          // 36864
#define W4  (W_ / 4)           // 12

#define SH  (H_ + 2)           // 50 padded rows
#define SW  52                 // padded row stride (floats), 16B-aligned
#define SPLANE (SH * SW)       // 2600 (16B-aligned)
#define SMEM_FLOATS (3 * SPLANE)  // 7800 floats = 31200 B

__global__ __launch_bounds__(192, 7) void unfold3d_kernel(
    const float* __restrict__ x, float* __restrict__ out)
{
    __shared__ float s[SMEM_FLOATS];

    const int d  = blockIdx.x;          // 0..15
    const int bc = blockIdx.y;          // 0..127

    const int w4 = threadIdx.x;         // 0..11
    const int hb = threadIdx.y;         // 0..15
    const int tid = hb * 12 + w4;       // 0..191

    // ---- Phase 0: zero-fill smem (vectorized) ----
    {
        float4* s4 = reinterpret_cast<float4*>(s);
        const int n4 = SMEM_FLOATS / 4;             // 1950
        #pragma unroll
        for (int k = 0; k < (n4 + 191) / 192; k++) {
            int i = tid + k * 192;
            if (i < n4) s4[i] = make_float4(0.f, 0.f, 0.f, 0.f);
        }
    }
    __syncthreads();

    // ---- Phase 1: load 3 planes (d-1, d, d+1) into haloed smem ----
    {
        const float* __restrict__ xb = x + (size_t)bc * DHW;
        #pragma unroll
        for (int p = 0; p < 3; p++) {
            const int dd = d + p - 1;
            if ((unsigned)dd < (unsigned)D_) {
                const float* __restrict__ plane = xb + dd * HW;
                float* __restrict__ sp = s + p * SPLANE;
                #pragma unroll
                for (int k = 0; k < 3; k++) {
                    const int row = hb + k * 16;            // 0..47
                    float4 g = *reinterpret_cast<const float4*>(
                        plane + row * W_ + w4 * 4);
                    float* dst = sp + (row + 1) * SW + 1 + w4 * 4;
                    dst[0] = g.x; dst[1] = g.y; dst[2] = g.z; dst[3] = g.w;
                }
            }
        }
    }
    __syncthreads();

    // ---- Phase 2: branch-free store of 27 channel tiles ----
    // All (kd, kh, kw) offsets are compile-time immediates off one base per k.
    float* __restrict__ ob = out + (size_t)bc * 27 * DHW + (size_t)d * HW;

    #pragma unroll
    for (int k = 0; k < 3; k++) {
        const int h = hb + k * 16;                          // 0..47
        const float* __restrict__ sbase = s + h * SW + w4 * 4;   // padded (row h, col 4w4)
        float* __restrict__ obase = ob + h * W_ + w4 * 4;

        #pragma unroll
        for (int kd = 0; kd < 3; kd++) {
            #pragma unroll
            for (int kh = 0; kh < 3; kh++) {
                // q0 = padded cols [4w4 .. 4w4+3]  (input cols 4w4-1 .. 4w4+2)
                const float* p = sbase + kd * SPLANE + kh * SW;
                float4 q0 = *reinterpret_cast<const float4*>(p);
                float4 q1 = *reinterpret_cast<const float4*>(p + 4);

                float* o = obase + ((kd * 3 + kh) * 3) * DHW;
                __stcs(reinterpret_cast<float4*>(o), q0);
                __stcs(reinterpret_cast<float4*>(o + DHW),
                       make_float4(q0.y, q0.z, q0.w, q1.x));
                __stcs(reinterpret_cast<float4*>(o + 2 * DHW),
                       make_float4(q0.z, q0.w, q1.x, q1.y));
            }
        }
    }
}

extern "C" void kernel_launch(void* const* d_in, const int* in_sizes, int n_in,
                              void* d_out, int out_size)
{
    const float* x = (const float*)d_in[0];
    float* out = (float*)d_out;

    dim3 grid(D_, B_ * C_);        // 16 x 128 = 2048 blocks
    dim3 block(W4, 16);            // 192 threads
    unfold3d_kernel<<<grid, block>>>(x, out);
}

// round 5
// speedup vs baseline: 1.6982x; 1.0039x over previous
#include <cuda_runtime.h>
#include <cuda_bf16.h>
#include <cstdint>

// Unfold3d: x (B=4, C=32, D=16, H=48, W=48) fp32, K=3, PAD=1, STR=1, DIL=1.
// out[b][c*27 + kidx][d*HW + h*W + w] = x[b][c][d+kd-1][h+kh-1][w+kw-1] (0 OOB)
//
// R5: occupancy push. Packed (halo-free) smem planes 3x48x48 = 27.6KB ->
// 8 CTAs/SM (48 warps, 75% theoretical occ). Row halo handled by predicated
// LDS (uniform per row); column halo by two predicated scalar LDS. Phase-1 is
// a straight float4 plane copy (smem layout == gmem layout); zero-fill only
// for d-OOB planes. __stcs streaming stores.

#define B_  4
#define C_  32
#define D_  16
#define H_  48
#define W_  48
#define HW  (H_ * W_)          // 2304
#define DHW (D_ * HW)          // 36864
#define W4  (W_ / 4)           // 12
#define SPLANE HW              // packed plane, 2304 floats
#define SMEM_FLOATS (3 * SPLANE)  // 6912 floats = 27648 B

__global__ __launch_bounds__(192, 8) void unfold3d_kernel(
    const float* __restrict__ x, float* __restrict__ out)
{
    __shared__ float s[SMEM_FLOATS];

    const int d  = blockIdx.x;          // 0..15
    const int bc = blockIdx.y;          // 0..127

    const int w4 = threadIdx.x;         // 0..11
    const int hb = threadIdx.y;         // 0..15

    // ---- Phase 1: copy 3 planes (d-1, d, d+1) into packed smem ----
    {
        const float* __restrict__ xb = x + (size_t)bc * DHW;
        #pragma unroll
        for (int p = 0; p < 3; p++) {
            const int dd = d + p - 1;
            float* __restrict__ sp = s + p * SPLANE;
            if ((unsigned)dd < (unsigned)D_) {
                const float* __restrict__ plane = xb + dd * HW;
                #pragma unroll
                for (int k = 0; k < 3; k++) {
                    const int r = hb + k * 16;
                    *reinterpret_cast<float4*>(sp + r * W_ + w4 * 4) =
                        *reinterpret_cast<const float4*>(plane + r * W_ + w4 * 4);
                }
            } else {
                #pragma unroll
                for (int k = 0; k < 3; k++) {
                    const int r = hb + k * 16;
                    *reinterpret_cast<float4*>(sp + r * W_ + w4 * 4) =
                        make_float4(0.f, 0.f, 0.f, 0.f);
                }
            }
        }
    }
    __syncthreads();

    // ---- Phase 2: 27 channel tiles, predicated edges ----
    float* __restrict__ ob = out + (size_t)bc * 27 * DHW + (size_t)d * HW;

    #pragma unroll
    for (int k = 0; k < 3; k++) {
        const int h = hb + k * 16;                    // 0..47
        float* __restrict__ obase = ob + h * W_ + w4 * 4;

        #pragma unroll
        for (int kh = 0; kh < 3; kh++) {
            const int hh = h + kh - 1;                // -1..48
            const bool rok = (unsigned)hh < (unsigned)H_;

            #pragma unroll
            for (int kd = 0; kd < 3; kd++) {
                const float* __restrict__ p =
                    s + kd * SPLANE + hh * W_ + w4 * 4;

                float4 q = make_float4(0.f, 0.f, 0.f, 0.f);
                float pw = 0.f, nx = 0.f;
                if (rok) {
                    q = *reinterpret_cast<const float4*>(p);
                    if (w4 > 0)       pw = p[-1];     // input col 4w4-1
                    if (w4 < W4 - 1)  nx = p[4];      // input col 4w4+4
                }

                float* o = obase + ((kd * 3 + kh) * 3) * DHW;
                __stcs(reinterpret_cast<float4*>(o),
                       make_float4(pw, q.x, q.y, q.z));            // kw=0
                __stcs(reinterpret_cast<float4*>(o + DHW), q);     // kw=1
                __stcs(reinterpret_cast<float4*>(o + 2 * DHW),
                       make_float4(q.y, q.z, q.w, nx));            // kw=2
            }
        }
    }
}

extern "C" void kernel_launch(void* const* d_in, const int* in_sizes, int n_in,
                              void* d_out, int out_size)
{
    const float* x = (const float*)d_in[0];
    float* out = (float*)d_out;

    dim3 grid(D_, B_ * C_);        // 16 x 128 = 2048 blocks
    dim3 block(W4, 16);            // 192 threads
    unfold3d_kernel<<<grid, block>>>(x, out);
}